// round 5
// baseline (speedup 1.0000x reference)
#include <cuda_runtime.h>
#include <math.h>

// Problem constants
#define G_    64
#define NPG   256
#define EPG   4096
#define NN    (G_*NPG)     // 16384 nodes
#define EE    (G_*EPG)     // 262144 edges
#define IN_C  256
#define OHC_  8
#define HH    4
#define CC    64
#define HC    256          // H*C
#define KDIM  (IN_C+OHC_)  // 264

// Scratch (device globals; no allocation allowed)
__device__ int   g_deg[NN];
__device__ int   g_off[NN];
__device__ int   g_cur[NN];
__device__ int   g_esrc[EE];
__device__ __align__(16) float g_ohfeat[NN*OHC_];
__device__ __align__(16) float g_xp[NN*HC];
__device__ __align__(16) float g_al[NN*HH];
__device__ __align__(16) float g_ar[NN*HH];

// ---------------------------------------------------------------------------
// 1. Fused CSR prefix: per-graph smem histogram + scan (one block per graph)
__global__ void __launch_bounds__(256) k_csr(const int* __restrict__ adjs) {
    __shared__ int sdeg[NPG];
    __shared__ int s[NPG];
    int g = blockIdx.x, t = threadIdx.x;
    sdeg[t] = 0;
    __syncthreads();
    const int* dsts = adjs + g * 2 * EPG + EPG;
#pragma unroll 4
    for (int e = t; e < EPG; e += 256)
        atomicAdd(&sdeg[dsts[e]], 1);
    __syncthreads();
    int d = sdeg[t];
    s[t] = d;
    for (int o = 1; o < NPG; o <<= 1) {
        __syncthreads();
        int v = (t >= o) ? s[t - o] : 0;
        __syncthreads();
        s[t] += v;
    }
    __syncthreads();
    int off = g * EPG + s[t] - d;   // exclusive prefix + graph base
    g_deg[g * NPG + t] = d;
    g_off[g * NPG + t] = off;
    g_cur[g * NPG + t] = off;
}

// 2. Scatter source ids into CSR slots
__global__ void k_scatter(const int* __restrict__ adjs) {
    int e  = blockIdx.x * 256 + threadIdx.x;
    if (e >= EE) return;
    int g  = e >> 12;
    int le = e & (EPG - 1);
    int base = g * 2 * EPG;
    int src = adjs[base + le];
    int dst = adjs[base + EPG + le];
    int pos = atomicAdd(&g_cur[g * NPG + dst], 1);
    g_esrc[pos] = g * NPG + src;
}

// ---------------------------------------------------------------------------
// 3. Per-node: sort row (register bitonic + shfl), conv1(1->8), conv2(8->16),
//    mean, fc -> oh_feat
__global__ void __launch_bounds__(256) k_conv(
    const float* __restrict__ oh,
    const float* __restrict__ w1, const float* __restrict__ b1,
    const float* __restrict__ w2, const float* __restrict__ b2,
    const float* __restrict__ fcw, const float* __restrict__ fcb)
{
    __shared__ float s[256];
    __shared__ float z1[8][258];
    __shared__ float sw2[16 * 24];
    __shared__ float sp[8 * 16];
    __shared__ float smean[16];

    int n = blockIdx.x, t = threadIdx.x;

    for (int i = t; i < 384; i += 256) sw2[i] = w2[i];

    // --- bitonic sort, value in register; shfl for j<32, smem for j>=32 ---
    float v = oh[(size_t)n * 256 + t];
#pragma unroll
    for (int k = 2; k <= 256; k <<= 1) {
        for (int j = k >> 1; j > 0; j >>= 1) {
            float o;
            if (j >= 32) {
                __syncthreads();
                s[t] = v;
                __syncthreads();
                o = s[t ^ j];
            } else {
                o = __shfl_xor_sync(0xffffffffu, v, j);
            }
            bool up    = ((t & k) == 0);
            bool lower = ((t & j) == 0);
            v = (lower == up) ? fminf(v, o) : fmaxf(v, o);
        }
    }
    __syncthreads();
    s[t] = v;
    __syncthreads();

    // --- conv1: 1 -> 8 channels, k=3, zero 'same' padding, relu ---
    float left  = (t > 0)   ? s[t - 1] : 0.f;
    float mid   = s[t];
    float right = (t < 255) ? s[t + 1] : 0.f;
#pragma unroll
    for (int oc = 0; oc < 8; oc++) {
        float z = b1[oc] + w1[oc*3 + 0]*left + w1[oc*3 + 1]*mid + w1[oc*3 + 2]*right;
        z1[oc][t + 1] = fmaxf(z, 0.f);
    }
    if (t < 8)       z1[t][0]       = 0.f;
    else if (t < 16) z1[t - 8][257] = 0.f;
    __syncthreads();

    // --- conv2: 8 -> 16 channels, relu ---
    float tap[24];
#pragma unroll
    for (int ic = 0; ic < 8; ic++) {
        tap[ic*3 + 0] = z1[ic][t];
        tap[ic*3 + 1] = z1[ic][t + 1];
        tap[ic*3 + 2] = z1[ic][t + 2];
    }
    float acc[16];
#pragma unroll
    for (int oc = 0; oc < 16; oc++) {
        float z = b2[oc];
#pragma unroll
        for (int j = 0; j < 24; j++) z = fmaf(sw2[oc*24 + j], tap[j], z);
        acc[oc] = fmaxf(z, 0.f);
    }

    // block reduction over L for the 16 channels
    int lane = t & 31, wid = t >> 5;
#pragma unroll
    for (int oc = 0; oc < 16; oc++) {
        float z = acc[oc];
#pragma unroll
        for (int o = 16; o > 0; o >>= 1) z += __shfl_down_sync(0xffffffffu, z, o);
        if (lane == 0) sp[wid * 16 + oc] = z;
    }
    __syncthreads();
    if (t < 16) {
        float m = 0.f;
#pragma unroll
        for (int w = 0; w < 8; w++) m += sp[w * 16 + t];
        smean[t] = m * (1.0f / 256.0f);
    }
    __syncthreads();
    if (t < 8) {
        float z = fcb[t];
#pragma unroll
        for (int ic = 0; ic < 16; ic++) z = fmaf(smean[ic], fcw[ic * 8 + t], z);
        g_ohfeat[n * 8 + t] = z;
    }
}

// ---------------------------------------------------------------------------
// 4. Tensor-core GEMM: xp = [x | oh_feat] @ lin_w  (tf32 mma.sync)
//    Block tile 128x64 (one head per block-col), BK=32, 8 warps @ 32x32 each.
//    Fused alpha_l / alpha_r epilogue (block-local: head == block col).
__device__ __forceinline__ unsigned f2tf32(float f) {
    unsigned u;
    asm("cvt.rna.tf32.f32 %0, %1;" : "=r"(u) : "f"(f));
    return u;
}

__global__ void __launch_bounds__(256) k_gemm(
    const float* __restrict__ x, const float* __restrict__ lw,
    const float* __restrict__ attl, const float* __restrict__ attr)
{
    __shared__ unsigned sA[128][36];   // [m][k] pad 36: frag banks (4m+k)%32 distinct
    __shared__ unsigned sB[32][72];    // [k][n] pad 72: frag banks (8k+n)%32 distinct
    __shared__ float sattl[64], sattr[64];
    __shared__ float sredl[2][128], sredr[2][128];

    int t  = threadIdx.x;
    int bm = blockIdx.x, bn = blockIdx.y;      // bn == head
    int n0 = bm * 128;
    int w = t >> 5, lane = t & 31;
    int wm = w & 3, wn = w >> 2;
    int gid = lane >> 2, tig = lane & 3;

    if (t < 64) { sattl[t] = attl[bn * 64 + t]; sattr[t] = attr[bn * 64 + t]; }

    float c[2][4][4];
#pragma unroll
    for (int mt = 0; mt < 2; mt++)
#pragma unroll
        for (int nt = 0; nt < 4; nt++)
#pragma unroll
            for (int q = 0; q < 4; q++) c[mt][nt][q] = 0.f;

    for (int kb = 0; kb < 9; kb++) {           // 9*32 = 288 >= 264, zero-fill tail
        int k0 = kb * 32;
        __syncthreads();
        // load A tile (128 rows x 32 k), coalesced scalar loads
#pragma unroll
        for (int i = 0; i < 16; i++) {
            int idx = i * 256 + t;
            int r = idx >> 5, cc = idx & 31;
            int k = k0 + cc;
            float v = 0.f;
            if (k < 256)       v = x[(size_t)(n0 + r) * 256 + k];
            else if (k < 264)  v = g_ohfeat[(n0 + r) * 8 + (k - 256)];
            sA[r][cc] = f2tf32(v);
        }
        // load B tile (32 k x 64 n)
#pragma unroll
        for (int i = 0; i < 8; i++) {
            int idx = i * 256 + t;
            int kk = idx >> 6, nn = idx & 63;
            int k = k0 + kk;
            float v = (k < 264) ? lw[(size_t)k * 256 + bn * 64 + nn] : 0.f;
            sB[kk][nn] = f2tf32(v);
        }
        __syncthreads();

#pragma unroll
        for (int ks = 0; ks < 4; ks++) {
            int kbv = ks * 8;
            unsigned a[2][4], b[4][2];
#pragma unroll
            for (int mt = 0; mt < 2; mt++) {
                int m = wm * 32 + mt * 16 + gid;
                a[mt][0] = sA[m    ][kbv + tig];
                a[mt][1] = sA[m + 8][kbv + tig];
                a[mt][2] = sA[m    ][kbv + tig + 4];
                a[mt][3] = sA[m + 8][kbv + tig + 4];
            }
#pragma unroll
            for (int nt = 0; nt < 4; nt++) {
                int n = wn * 32 + nt * 8 + gid;
                b[nt][0] = sB[kbv + tig    ][n];
                b[nt][1] = sB[kbv + tig + 4][n];
            }
#pragma unroll
            for (int mt = 0; mt < 2; mt++)
#pragma unroll
                for (int nt = 0; nt < 4; nt++)
                    asm volatile(
                        "mma.sync.aligned.m16n8k8.row.col.f32.tf32.tf32.f32 "
                        "{%0,%1,%2,%3}, {%4,%5,%6,%7}, {%8,%9}, {%0,%1,%2,%3};"
                        : "+f"(c[mt][nt][0]), "+f"(c[mt][nt][1]),
                          "+f"(c[mt][nt][2]), "+f"(c[mt][nt][3])
                        : "r"(a[mt][0]), "r"(a[mt][1]), "r"(a[mt][2]), "r"(a[mt][3]),
                          "r"(b[nt][0]), "r"(b[nt][1]));
        }
    }

    // ---- store xp ----
#pragma unroll
    for (int mt = 0; mt < 2; mt++) {
        int r0 = wm * 32 + mt * 16 + gid;
#pragma unroll
        for (int nt = 0; nt < 4; nt++) {
            int gcol = bn * 64 + wn * 32 + nt * 8 + tig * 2;
            *(float2*)&g_xp[(size_t)(n0 + r0)     * 256 + gcol] =
                make_float2(c[mt][nt][0], c[mt][nt][1]);
            *(float2*)&g_xp[(size_t)(n0 + r0 + 8) * 256 + gcol] =
                make_float2(c[mt][nt][2], c[mt][nt][3]);
        }
    }

    // ---- fused alpha (this block's head = bn) ----
    float pl[4] = {0.f, 0.f, 0.f, 0.f};
    float pr[4] = {0.f, 0.f, 0.f, 0.f};
#pragma unroll
    for (int mt = 0; mt < 2; mt++)
#pragma unroll
        for (int nt = 0; nt < 4; nt++) {
            int cl = wn * 32 + nt * 8 + tig * 2;
            float wl0 = sattl[cl], wl1 = sattl[cl + 1];
            float wr0 = sattr[cl], wr1 = sattr[cl + 1];
            pl[mt*2+0] += c[mt][nt][0]*wl0 + c[mt][nt][1]*wl1;
            pl[mt*2+1] += c[mt][nt][2]*wl0 + c[mt][nt][3]*wl1;
            pr[mt*2+0] += c[mt][nt][0]*wr0 + c[mt][nt][1]*wr1;
            pr[mt*2+1] += c[mt][nt][2]*wr0 + c[mt][nt][3]*wr1;
        }
    // reduce across the 4 lanes of each group (tig)
#pragma unroll
    for (int o = 2; o > 0; o >>= 1)
#pragma unroll
        for (int q = 0; q < 4; q++) {
            pl[q] += __shfl_down_sync(0xffffffffu, pl[q], o, 4);
            pr[q] += __shfl_down_sync(0xffffffffu, pr[q], o, 4);
        }
    if (tig == 0) {
#pragma unroll
        for (int mt = 0; mt < 2; mt++)
#pragma unroll
            for (int sb = 0; sb < 2; sb++) {
                int r = wm * 32 + mt * 16 + sb * 8 + gid;
                sredl[wn][r] = pl[mt*2+sb];
                sredr[wn][r] = pr[mt*2+sb];
            }
    }
    __syncthreads();
    if (t < 128) {
        g_al[(n0 + t) * 4 + bn] = sredl[0][t] + sredl[1][t];
        g_ar[(n0 + t) * 4 + bn] = sredr[0][t] + sredr[1][t];
    }
}

// ---------------------------------------------------------------------------
// 5. Combined gather-side aggregation: attention softmax-weighted sum of xp,
//    and onehot row scatter-add (gather form) + residual.
#define CHUNK 128
__global__ void __launch_bounds__(256) k_agg(
    const float* __restrict__ oh,
    const float* __restrict__ bias,
    float* __restrict__ out)
{
    __shared__ int   ssrc[CHUNK];
    __shared__ float sal[CHUNK * 4];

    int n = blockIdx.x, t = threadIdx.x;
    int g = n >> 8;
    int h = t >> 6;
    float arh = g_ar[n * 4 + h];
    const float* ohg = oh + (size_t)g * (NPG * NPG);

    float accx = 0.f, den = 0.f;
    float acco = ohg[(size_t)(n & 255) * 256 + t];   // residual term

    int beg = g_off[n];
    int cnt = g_deg[n];

    for (int c0 = 0; c0 < cnt; c0 += CHUNK) {
        int m = min(CHUNK, cnt - c0);
        __syncthreads();
        if (t < m) {
            int s = g_esrc[beg + c0 + t];
            ssrc[t] = s;
            float4 v = *(const float4*)&g_al[s * 4];
            sal[t*4 + 0] = v.x; sal[t*4 + 1] = v.y;
            sal[t*4 + 2] = v.z; sal[t*4 + 3] = v.w;
        }
        __syncthreads();
#pragma unroll 4
        for (int i = 0; i < m; i++) {
            int s = ssrc[i];
            float l = sal[i*4 + h] + arh;
            l = (l > 0.f) ? l : 0.2f * l;              // leaky_relu
            float w = __expf(l);
            den  += w;
            accx  = fmaf(w, g_xp[(size_t)s * 256 + t], accx);
            acco += ohg[(size_t)(s & 255) * 256 + t];
        }
    }

    out[(size_t)n * 256 + t] = accx / (den + 1e-16f) + bias[t];
    out[(size_t)NN * 256 + (size_t)n * 256 + t] = acco;
}

// ---------------------------------------------------------------------------
extern "C" void kernel_launch(void* const* d_in, const int* in_sizes, int n_in,
                              void* d_out, int out_size)
{
    const float* x     = (const float*)d_in[0];
    const float* oh    = (const float*)d_in[1];
    const int*   adjs  = (const int*)d_in[2];
    const float* lin_w = (const float*)d_in[3];
    const float* att_l = (const float*)d_in[4];
    const float* att_r = (const float*)d_in[5];
    const float* bias  = (const float*)d_in[6];
    const float* c1w   = (const float*)d_in[7];
    const float* c1b   = (const float*)d_in[8];
    const float* c2w   = (const float*)d_in[9];
    const float* c2b   = (const float*)d_in[10];
    const float* fcw   = (const float*)d_in[11];
    const float* fcb   = (const float*)d_in[12];
    float* out = (float*)d_out;

    // CSR build
    k_csr<<<G_, 256>>>(adjs);
    k_scatter<<<EE / 256, 256>>>(adjs);

    // node features
    k_conv<<<NN, 256>>>(oh, c1w, c1b, c2w, c2b, fcw, fcb);
    dim3 ggrid(NN / 128, 4);
    k_gemm<<<ggrid, 256>>>(x, lin_w, att_l, att_r);

    // aggregation + outputs
    k_agg<<<NN, 256>>>(oh, bias, out);
}

// round 6
// speedup vs baseline: 1.0934x; 1.0934x over previous
#include <cuda_runtime.h>
#include <math.h>

// Problem constants
#define G_    64
#define NPG   256
#define EPG   4096
#define NN    (G_*NPG)     // 16384 nodes
#define EE    (G_*EPG)     // 262144 edges
#define IN_C  256
#define OHC_  8
#define HH    4
#define CC    64
#define HC    256          // H*C
#define KDIM  (IN_C+OHC_)  // 264

// Scratch (device globals; no allocation allowed)
__device__ int   g_deg[NN];
__device__ int   g_off[NN];
__device__ int   g_cur[NN];
__device__ int   g_esrc[EE];
__device__ __align__(16) float g_ohfeat[NN*OHC_];
__device__ __align__(16) float g_xp[NN*HC];
__device__ __align__(16) float g_al[NN*HH];
__device__ __align__(16) float g_ar[NN*HH];

// ---------------------------------------------------------------------------
// 1. Fused CSR prefix: per-graph smem histogram + scan (one block per graph)
__global__ void __launch_bounds__(256) k_csr(const int* __restrict__ adjs) {
    __shared__ int sdeg[NPG];
    __shared__ int s[NPG];
    int g = blockIdx.x, t = threadIdx.x;
    sdeg[t] = 0;
    __syncthreads();
    const int* dsts = adjs + g * 2 * EPG + EPG;
#pragma unroll 4
    for (int e = t; e < EPG; e += 256)
        atomicAdd(&sdeg[dsts[e]], 1);
    __syncthreads();
    int d = sdeg[t];
    s[t] = d;
    for (int o = 1; o < NPG; o <<= 1) {
        __syncthreads();
        int v = (t >= o) ? s[t - o] : 0;
        __syncthreads();
        s[t] += v;
    }
    __syncthreads();
    int off = g * EPG + s[t] - d;   // exclusive prefix + graph base
    g_deg[g * NPG + t] = d;
    g_off[g * NPG + t] = off;
    g_cur[g * NPG + t] = off;
}

// 2. Scatter source ids into CSR slots
__global__ void k_scatter(const int* __restrict__ adjs) {
    int e  = blockIdx.x * 256 + threadIdx.x;
    if (e >= EE) return;
    int g  = e >> 12;
    int le = e & (EPG - 1);
    int base = g * 2 * EPG;
    int src = adjs[base + le];
    int dst = adjs[base + EPG + le];
    int pos = atomicAdd(&g_cur[g * NPG + dst], 1);
    g_esrc[pos] = g * NPG + src;
}

// ---------------------------------------------------------------------------
// 3. Per-node: sort row (register bitonic + shfl), conv1(1->8), conv2(8->16),
//    mean, fc -> oh_feat
__global__ void __launch_bounds__(256) k_conv(
    const float* __restrict__ oh,
    const float* __restrict__ w1, const float* __restrict__ b1,
    const float* __restrict__ w2, const float* __restrict__ b2,
    const float* __restrict__ fcw, const float* __restrict__ fcb)
{
    __shared__ float s[256];
    __shared__ float z1[8][258];
    __shared__ float sw2[16 * 24];
    __shared__ float sp[8 * 16];
    __shared__ float smean[16];

    int n = blockIdx.x, t = threadIdx.x;

    for (int i = t; i < 384; i += 256) sw2[i] = w2[i];

    // --- bitonic sort, value in register; shfl for j<32, smem for j>=32 ---
    float v = oh[(size_t)n * 256 + t];
#pragma unroll
    for (int k = 2; k <= 256; k <<= 1) {
        for (int j = k >> 1; j > 0; j >>= 1) {
            float o;
            if (j >= 32) {
                __syncthreads();
                s[t] = v;
                __syncthreads();
                o = s[t ^ j];
            } else {
                o = __shfl_xor_sync(0xffffffffu, v, j);
            }
            bool up    = ((t & k) == 0);
            bool lower = ((t & j) == 0);
            v = (lower == up) ? fminf(v, o) : fmaxf(v, o);
        }
    }
    __syncthreads();
    s[t] = v;
    __syncthreads();

    // --- conv1: 1 -> 8 channels, k=3, zero 'same' padding, relu ---
    float left  = (t > 0)   ? s[t - 1] : 0.f;
    float mid   = s[t];
    float right = (t < 255) ? s[t + 1] : 0.f;
#pragma unroll
    for (int oc = 0; oc < 8; oc++) {
        float z = b1[oc] + w1[oc*3 + 0]*left + w1[oc*3 + 1]*mid + w1[oc*3 + 2]*right;
        z1[oc][t + 1] = fmaxf(z, 0.f);
    }
    if (t < 8)       z1[t][0]       = 0.f;
    else if (t < 16) z1[t - 8][257] = 0.f;
    __syncthreads();

    // --- conv2: 8 -> 16 channels, relu ---
    float tap[24];
#pragma unroll
    for (int ic = 0; ic < 8; ic++) {
        tap[ic*3 + 0] = z1[ic][t];
        tap[ic*3 + 1] = z1[ic][t + 1];
        tap[ic*3 + 2] = z1[ic][t + 2];
    }
    float acc[16];
#pragma unroll
    for (int oc = 0; oc < 16; oc++) {
        float z = b2[oc];
#pragma unroll
        for (int j = 0; j < 24; j++) z = fmaf(sw2[oc*24 + j], tap[j], z);
        acc[oc] = fmaxf(z, 0.f);
    }

    // --- multi-channel butterfly reduce over the 32 lanes ---
    // after this, lane l of each warp holds sum over its warp's 32 L-positions
    // for channel (l>>1)
    int lane = t & 31, wid = t >> 5;
    {
        bool lo = (lane & 16) == 0;
#pragma unroll
        for (int c2 = 0; c2 < 8; c2++) {
            float give = lo ? acc[c2 + 8] : acc[c2];
            float keep = lo ? acc[c2]     : acc[c2 + 8];
            acc[c2] = keep + __shfl_xor_sync(0xffffffffu, give, 16);
        }
    }
    {
        bool lo = (lane & 8) == 0;
#pragma unroll
        for (int c2 = 0; c2 < 4; c2++) {
            float give = lo ? acc[c2 + 4] : acc[c2];
            float keep = lo ? acc[c2]     : acc[c2 + 4];
            acc[c2] = keep + __shfl_xor_sync(0xffffffffu, give, 8);
        }
    }
    {
        bool lo = (lane & 4) == 0;
#pragma unroll
        for (int c2 = 0; c2 < 2; c2++) {
            float give = lo ? acc[c2 + 2] : acc[c2];
            float keep = lo ? acc[c2]     : acc[c2 + 2];
            acc[c2] = keep + __shfl_xor_sync(0xffffffffu, give, 4);
        }
    }
    {
        bool lo = (lane & 2) == 0;
        float give = lo ? acc[1] : acc[0];
        float keep = lo ? acc[0] : acc[1];
        acc[0] = keep + __shfl_xor_sync(0xffffffffu, give, 2);
    }
    acc[0] += __shfl_xor_sync(0xffffffffu, acc[0], 1);
    if ((lane & 1) == 0) sp[wid * 16 + (lane >> 1)] = acc[0];
    __syncthreads();
    if (t < 16) {
        float m = 0.f;
#pragma unroll
        for (int w = 0; w < 8; w++) m += sp[w * 16 + t];
        smean[t] = m * (1.0f / 256.0f);
    }
    __syncthreads();
    if (t < 8) {
        float z = fcb[t];
#pragma unroll
        for (int ic = 0; ic < 16; ic++) z = fmaf(smean[ic], fcw[ic * 8 + t], z);
        g_ohfeat[n * 8 + t] = z;
    }
}

// ---------------------------------------------------------------------------
// 4. Tensor-core GEMM: xp = [x | oh_feat] @ lin_w  (tf32 mma.sync)
//    Block tile 128x64 (one head per block-col), BK=32, 8 warps @ 32x32 each.
//    Smem tiles stored in MMA FRAGMENT ORDER: one LDS.128 per A fragment,
//    one LDS.64 per B fragment. Fused alpha_l/alpha_r epilogue.
__device__ __forceinline__ unsigned f2tf32(float f) {
    unsigned u;
    asm("cvt.rna.tf32.f32 %0, %1;" : "=r"(u) : "f"(f));
    return u;
}

__global__ void __launch_bounds__(256) k_gemm(
    const float* __restrict__ x, const float* __restrict__ lw,
    const float* __restrict__ attl, const float* __restrict__ attr)
{
    __shared__ uint4 sAf[8][4][32];    // [m_tile][k_tile][lane] = {a0,a1,a2,a3}
    __shared__ uint2 sBf[8][4][32];    // [n_tile][k_tile][lane] = {b0,b1}
    __shared__ float sattl[64], sattr[64];
    __shared__ float sredl[2][128], sredr[2][128];

    int t  = threadIdx.x;
    int bm = blockIdx.x, bn = blockIdx.y;      // bn == head
    int n0 = bm * 128;
    int w = t >> 5, lane = t & 31;
    int wm = w & 3, wn = w >> 2;
    int gid = lane >> 2, tig = lane & 3;

    if (t < 64) { sattl[t] = attl[bn * 64 + t]; sattr[t] = attr[bn * 64 + t]; }

    float c[2][4][4];
#pragma unroll
    for (int mt = 0; mt < 2; mt++)
#pragma unroll
        for (int nt = 0; nt < 4; nt++)
#pragma unroll
            for (int q = 0; q < 4; q++) c[mt][nt][q] = 0.f;

    for (int kb = 0; kb < 9; kb++) {           // 9*32 = 288 >= 264, zero-fill tail
        int k0 = kb * 32;
        __syncthreads();
        // ---- stage A (128 x 32) in fragment order ----
#pragma unroll
        for (int i = 0; i < 16; i++) {
            int idx = i * 256 + t;
            int r = idx >> 5, cc = idx & 31;
            int k = k0 + cc;
            float v = 0.f;
            if (k < 256)       v = x[(size_t)(n0 + r) * 256 + k];
            else if (k < 264)  v = g_ohfeat[(n0 + r) * 8 + (k - 256)];
            int mt = r >> 4, rr = r & 15, kt = cc >> 3, kk = cc & 7;
            int hm = rr >> 3, gg = rr & 7, hk = kk >> 2, tt = kk & 3;
            ((unsigned*)&sAf[mt][kt][gg * 4 + tt])[hm + 2 * hk] = f2tf32(v);
        }
        // ---- stage B (32 x 64) in fragment order ----
#pragma unroll
        for (int i = 0; i < 8; i++) {
            int idx = i * 256 + t;
            int kk = idx >> 6, nn = idx & 63;
            int k = k0 + kk;
            float v = (k < 264) ? lw[(size_t)k * 256 + bn * 64 + nn] : 0.f;
            int nt = nn >> 3, gg = nn & 7, kt = kk >> 3, kr = kk & 7;
            int hk = kr >> 2, tt = kr & 3;
            ((unsigned*)&sBf[nt][kt][gg * 4 + tt])[hk] = f2tf32(v);
        }
        __syncthreads();

#pragma unroll
        for (int ks = 0; ks < 4; ks++) {
            uint4 a[2];
            uint2 b[4];
            a[0] = sAf[wm * 2 + 0][ks][lane];
            a[1] = sAf[wm * 2 + 1][ks][lane];
#pragma unroll
            for (int nt = 0; nt < 4; nt++) b[nt] = sBf[wn * 4 + nt][ks][lane];
#pragma unroll
            for (int mt = 0; mt < 2; mt++)
#pragma unroll
                for (int nt = 0; nt < 4; nt++)
                    asm volatile(
                        "mma.sync.aligned.m16n8k8.row.col.f32.tf32.tf32.f32 "
                        "{%0,%1,%2,%3}, {%4,%5,%6,%7}, {%8,%9}, {%0,%1,%2,%3};"
                        : "+f"(c[mt][nt][0]), "+f"(c[mt][nt][1]),
                          "+f"(c[mt][nt][2]), "+f"(c[mt][nt][3])
                        : "r"(a[mt].x), "r"(a[mt].y), "r"(a[mt].z), "r"(a[mt].w),
                          "r"(b[nt].x), "r"(b[nt].y));
        }
    }

    // ---- store xp ----
#pragma unroll
    for (int mt = 0; mt < 2; mt++) {
        int r0 = wm * 32 + mt * 16 + gid;
#pragma unroll
        for (int nt = 0; nt < 4; nt++) {
            int gcol = bn * 64 + wn * 32 + nt * 8 + tig * 2;
            *(float2*)&g_xp[(size_t)(n0 + r0)     * 256 + gcol] =
                make_float2(c[mt][nt][0], c[mt][nt][1]);
            *(float2*)&g_xp[(size_t)(n0 + r0 + 8) * 256 + gcol] =
                make_float2(c[mt][nt][2], c[mt][nt][3]);
        }
    }

    // ---- fused alpha (this block's head = bn) ----
    float pl[4] = {0.f, 0.f, 0.f, 0.f};
    float pr[4] = {0.f, 0.f, 0.f, 0.f};
#pragma unroll
    for (int mt = 0; mt < 2; mt++)
#pragma unroll
        for (int nt = 0; nt < 4; nt++) {
            int cl = wn * 32 + nt * 8 + tig * 2;
            float wl0 = sattl[cl], wl1 = sattl[cl + 1];
            float wr0 = sattr[cl], wr1 = sattr[cl + 1];
            pl[mt*2+0] += c[mt][nt][0]*wl0 + c[mt][nt][1]*wl1;
            pl[mt*2+1] += c[mt][nt][2]*wl0 + c[mt][nt][3]*wl1;
            pr[mt*2+0] += c[mt][nt][0]*wr0 + c[mt][nt][1]*wr1;
            pr[mt*2+1] += c[mt][nt][2]*wr0 + c[mt][nt][3]*wr1;
        }
#pragma unroll
    for (int o = 2; o > 0; o >>= 1)
#pragma unroll
        for (int q = 0; q < 4; q++) {
            pl[q] += __shfl_down_sync(0xffffffffu, pl[q], o, 4);
            pr[q] += __shfl_down_sync(0xffffffffu, pr[q], o, 4);
        }
    if (tig == 0) {
#pragma unroll
        for (int mt = 0; mt < 2; mt++)
#pragma unroll
            for (int sb = 0; sb < 2; sb++) {
                int r = wm * 32 + mt * 16 + sb * 8 + gid;
                sredl[wn][r] = pl[mt*2+sb];
                sredr[wn][r] = pr[mt*2+sb];
            }
    }
    __syncthreads();
    if (t < 128) {
        g_al[(n0 + t) * 4 + bn] = sredl[0][t] + sredl[1][t];
        g_ar[(n0 + t) * 4 + bn] = sredr[0][t] + sredr[1][t];
    }
}

// ---------------------------------------------------------------------------
// 5. Combined gather-side aggregation: attention softmax-weighted sum of xp,
//    and onehot row scatter-add (gather form) + residual.
#define CHUNK 128
__global__ void __launch_bounds__(256) k_agg(
    const float* __restrict__ oh,
    const float* __restrict__ bias,
    float* __restrict__ out)
{
    __shared__ int   ssrc[CHUNK];
    __shared__ float sal[CHUNK * 4];

    int n = blockIdx.x, t = threadIdx.x;
    int g = n >> 8;
    int h = t >> 6;
    float arh = g_ar[n * 4 + h];
    const float* ohg = oh + (size_t)g * (NPG * NPG);

    float accx = 0.f, den = 0.f;
    float acco = ohg[(size_t)(n & 255) * 256 + t];   // residual term

    int beg = g_off[n];
    int cnt = g_deg[n];

    for (int c0 = 0; c0 < cnt; c0 += CHUNK) {
        int m = min(CHUNK, cnt - c0);
        __syncthreads();
        if (t < m) {
            int s = g_esrc[beg + c0 + t];
            ssrc[t] = s;
            float4 v = *(const float4*)&g_al[s * 4];
            sal[t*4 + 0] = v.x; sal[t*4 + 1] = v.y;
            sal[t*4 + 2] = v.z; sal[t*4 + 3] = v.w;
        }
        __syncthreads();
#pragma unroll 4
        for (int i = 0; i < m; i++) {
            int s = ssrc[i];
            float l = sal[i*4 + h] + arh;
            l = (l > 0.f) ? l : 0.2f * l;              // leaky_relu
            float w = __expf(l);
            den  += w;
            accx  = fmaf(w, g_xp[(size_t)s * 256 + t], accx);
            acco += ohg[(size_t)(s & 255) * 256 + t];
        }
    }

    out[(size_t)n * 256 + t] = accx / (den + 1e-16f) + bias[t];
    out[(size_t)NN * 256 + (size_t)n * 256 + t] = acco;
}

// ---------------------------------------------------------------------------
extern "C" void kernel_launch(void* const* d_in, const int* in_sizes, int n_in,
                              void* d_out, int out_size)
{
    const float* x     = (const float*)d_in[0];
    const float* oh    = (const float*)d_in[1];
    const int*   adjs  = (const int*)d_in[2];
    const float* lin_w = (const float*)d_in[3];
    const float* att_l = (const float*)d_in[4];
    const float* att_r = (const float*)d_in[5];
    const float* bias  = (const float*)d_in[6];
    const float* c1w   = (const float*)d_in[7];
    const float* c1b   = (const float*)d_in[8];
    const float* c2w   = (const float*)d_in[9];
    const float* c2b   = (const float*)d_in[10];
    const float* fcw   = (const float*)d_in[11];
    const float* fcb   = (const float*)d_in[12];
    float* out = (float*)d_out;

    // CSR build
    k_csr<<<G_, 256>>>(adjs);
    k_scatter<<<EE / 256, 256>>>(adjs);

    // node features
    k_conv<<<NN, 256>>>(oh, c1w, c1b, c2w, c2b, fcw, fcb);
    dim3 ggrid(NN / 128, 4);
    k_gemm<<<ggrid, 256>>>(x, lin_w, att_l, att_r);

    // aggregation + outputs
    k_agg<<<NN, 256>>>(oh, bias, out);
}

// round 7
// speedup vs baseline: 1.4363x; 1.3137x over previous
#include <cuda_runtime.h>
#include <math.h>

// Problem constants
#define G_    64
#define NPG   256
#define EPG   4096
#define NN    (G_*NPG)     // 16384 nodes
#define EE    (G_*EPG)     // 262144 edges
#define IN_C  256
#define OHC_  8
#define HH    4
#define CC    64
#define HC    256          // H*C
#define KDIM  (IN_C+OHC_)  // 264

// Scratch (device globals; no allocation allowed)
__device__ int   g_deg[NN];
__device__ int   g_off[NN];
__device__ int   g_cur[NN];
__device__ int   g_esrc[EE];
__device__ __align__(16) float g_ohfeat[NN*OHC_];
__device__ __align__(16) float g_xp[NN*HC];
__device__ __align__(16) float g_al[NN*HH];
__device__ __align__(16) float g_ar[NN*HH];

// ---------------------------------------------------------------------------
// 1. Fused CSR prefix: per-graph smem histogram + scan (one block per graph)
__global__ void __launch_bounds__(256) k_csr(const int* __restrict__ adjs) {
    __shared__ int sdeg[NPG];
    __shared__ int s[NPG];
    int g = blockIdx.x, t = threadIdx.x;
    sdeg[t] = 0;
    __syncthreads();
    const int* dsts = adjs + g * 2 * EPG + EPG;
#pragma unroll 4
    for (int e = t; e < EPG; e += 256)
        atomicAdd(&sdeg[dsts[e]], 1);
    __syncthreads();
    int d = sdeg[t];
    s[t] = d;
    for (int o = 1; o < NPG; o <<= 1) {
        __syncthreads();
        int v = (t >= o) ? s[t - o] : 0;
        __syncthreads();
        s[t] += v;
    }
    __syncthreads();
    int off = g * EPG + s[t] - d;   // exclusive prefix + graph base
    g_deg[g * NPG + t] = d;
    g_off[g * NPG + t] = off;
    g_cur[g * NPG + t] = off;
}

// 2. Scatter source ids into CSR slots
__global__ void k_scatter(const int* __restrict__ adjs) {
    int e  = blockIdx.x * 256 + threadIdx.x;
    if (e >= EE) return;
    int g  = e >> 12;
    int le = e & (EPG - 1);
    int base = g * 2 * EPG;
    int src = adjs[base + le];
    int dst = adjs[base + EPG + le];
    int pos = atomicAdd(&g_cur[g * NPG + dst], 1);
    g_esrc[pos] = g * NPG + src;
}

// ---------------------------------------------------------------------------
// 3. Per-node: sort row (register bitonic + shfl), conv1(1->8), conv2(8->16),
//    mean, fc -> oh_feat
__global__ void __launch_bounds__(256) k_conv(
    const float* __restrict__ oh,
    const float* __restrict__ w1, const float* __restrict__ b1,
    const float* __restrict__ w2, const float* __restrict__ b2,
    const float* __restrict__ fcw, const float* __restrict__ fcb)
{
    __shared__ float s[256];
    __shared__ float z1[8][258];
    __shared__ float sw2[16 * 24];
    __shared__ float sp[8 * 16];
    __shared__ float smean[16];

    int n = blockIdx.x, t = threadIdx.x;

    for (int i = t; i < 384; i += 256) sw2[i] = w2[i];

    // --- bitonic sort, value in register; shfl for j<32, smem for j>=32 ---
    float v = oh[(size_t)n * 256 + t];
#pragma unroll
    for (int k = 2; k <= 256; k <<= 1) {
        for (int j = k >> 1; j > 0; j >>= 1) {
            float o;
            if (j >= 32) {
                __syncthreads();
                s[t] = v;
                __syncthreads();
                o = s[t ^ j];
            } else {
                o = __shfl_xor_sync(0xffffffffu, v, j);
            }
            bool up    = ((t & k) == 0);
            bool lower = ((t & j) == 0);
            v = (lower == up) ? fminf(v, o) : fmaxf(v, o);
        }
    }
    __syncthreads();
    s[t] = v;
    __syncthreads();

    // --- conv1: 1 -> 8 channels, k=3, zero 'same' padding, relu ---
    float left  = (t > 0)   ? s[t - 1] : 0.f;
    float mid   = s[t];
    float right = (t < 255) ? s[t + 1] : 0.f;
#pragma unroll
    for (int oc = 0; oc < 8; oc++) {
        float z = b1[oc] + w1[oc*3 + 0]*left + w1[oc*3 + 1]*mid + w1[oc*3 + 2]*right;
        z1[oc][t + 1] = fmaxf(z, 0.f);
    }
    if (t < 8)       z1[t][0]       = 0.f;
    else if (t < 16) z1[t - 8][257] = 0.f;
    __syncthreads();

    // --- conv2: 8 -> 16 channels, relu ---
    float tap[24];
#pragma unroll
    for (int ic = 0; ic < 8; ic++) {
        tap[ic*3 + 0] = z1[ic][t];
        tap[ic*3 + 1] = z1[ic][t + 1];
        tap[ic*3 + 2] = z1[ic][t + 2];
    }
    float acc[16];
#pragma unroll
    for (int oc = 0; oc < 16; oc++) {
        float z = b2[oc];
#pragma unroll
        for (int j = 0; j < 24; j++) z = fmaf(sw2[oc*24 + j], tap[j], z);
        acc[oc] = fmaxf(z, 0.f);
    }

    // --- multi-channel butterfly reduce over the 32 lanes ---
    int lane = t & 31, wid = t >> 5;
    {
        bool lo = (lane & 16) == 0;
#pragma unroll
        for (int c2 = 0; c2 < 8; c2++) {
            float give = lo ? acc[c2 + 8] : acc[c2];
            float keep = lo ? acc[c2]     : acc[c2 + 8];
            acc[c2] = keep + __shfl_xor_sync(0xffffffffu, give, 16);
        }
    }
    {
        bool lo = (lane & 8) == 0;
#pragma unroll
        for (int c2 = 0; c2 < 4; c2++) {
            float give = lo ? acc[c2 + 4] : acc[c2];
            float keep = lo ? acc[c2]     : acc[c2 + 4];
            acc[c2] = keep + __shfl_xor_sync(0xffffffffu, give, 8);
        }
    }
    {
        bool lo = (lane & 4) == 0;
#pragma unroll
        for (int c2 = 0; c2 < 2; c2++) {
            float give = lo ? acc[c2 + 2] : acc[c2];
            float keep = lo ? acc[c2]     : acc[c2 + 2];
            acc[c2] = keep + __shfl_xor_sync(0xffffffffu, give, 4);
        }
    }
    {
        bool lo = (lane & 2) == 0;
        float give = lo ? acc[1] : acc[0];
        float keep = lo ? acc[0] : acc[1];
        acc[0] = keep + __shfl_xor_sync(0xffffffffu, give, 2);
    }
    acc[0] += __shfl_xor_sync(0xffffffffu, acc[0], 1);
    if ((lane & 1) == 0) sp[wid * 16 + (lane >> 1)] = acc[0];
    __syncthreads();
    if (t < 16) {
        float m = 0.f;
#pragma unroll
        for (int w = 0; w < 8; w++) m += sp[w * 16 + t];
        smean[t] = m * (1.0f / 256.0f);
    }
    __syncthreads();
    if (t < 8) {
        float z = fcb[t];
#pragma unroll
        for (int ic = 0; ic < 16; ic++) z = fmaf(smean[ic], fcw[ic * 8 + t], z);
        g_ohfeat[n * 8 + t] = z;
    }
}

// ---------------------------------------------------------------------------
// 4. Tensor-core GEMM with cp.async double buffering.
//    Block tile 128x64 (bn == head), BK=16, 17 tiles (16 from x, 1 tail).
//    A raw smem stride 20 (banks (20m+k)%32 distinct),
//    B raw smem stride 72 (banks (8k+n)%32 distinct). tf32 cvt at frag load.
__device__ __forceinline__ unsigned f2tf32(float f) {
    unsigned u;
    asm("cvt.rna.tf32.f32 %0, %1;" : "=r"(u) : "f"(f));
    return u;
}
__device__ __forceinline__ void cpa16(unsigned d, const void* s, int srcsize) {
    asm volatile("cp.async.cg.shared.global [%0], [%1], 16, %2;"
                 :: "r"(d), "l"(s), "r"(srcsize));
}

#define ASTRIDE 20
#define BSTRIDE 72

__global__ void __launch_bounds__(256) k_gemm(
    const float* __restrict__ x, const float* __restrict__ lw,
    const float* __restrict__ attl, const float* __restrict__ attr)
{
    __shared__ float sA[2][128 * ASTRIDE];
    __shared__ float sB[2][16 * BSTRIDE];
    __shared__ float sattl[64], sattr[64];
    __shared__ float sredl[2][128], sredr[2][128];

    int t  = threadIdx.x;
    int bm = blockIdx.x, bn = blockIdx.y;      // bn == head
    int n0 = bm * 128;
    int w = t >> 5, lane = t & 31;
    int wm = w & 3, wn = w >> 2;
    int gid = lane >> 2, tig = lane & 3;

    if (t < 64) { sattl[t] = attl[bn * 64 + t]; sattr[t] = attr[bn * 64 + t]; }

    unsigned sAaddr[2], sBaddr[2];
    sAaddr[0] = (unsigned)__cvta_generic_to_shared(&sA[0][0]);
    sAaddr[1] = (unsigned)__cvta_generic_to_shared(&sA[1][0]);
    sBaddr[0] = (unsigned)__cvta_generic_to_shared(&sB[0][0]);
    sBaddr[1] = (unsigned)__cvta_generic_to_shared(&sB[1][0]);

    // A staging coords: 512 float4 per tile -> 2/thread
    int ar0 = t >> 2,            ac0 = (t & 3) * 4;           // q = t
    int ar1 = (t + 256) >> 2,    ac1 = (t & 3) * 4;           // q = t+256
    // B staging coords: 256 float4 -> 1/thread
    int br  = t >> 4,            bc  = (t & 15) * 4;

    // stage(tile): issue cp.asyncs for tile index kt into buf kt&1
    auto stage = [&](int kt) {
        int b = kt & 1;
        unsigned da0 = sAaddr[b] + (ar0 * ASTRIDE + ac0) * 4;
        unsigned da1 = sAaddr[b] + (ar1 * ASTRIDE + ac1) * 4;
        unsigned db  = sBaddr[b] + (br  * BSTRIDE + bc ) * 4;
        if (kt < 16) {
            cpa16(da0, x + (size_t)(n0 + ar0) * 256 + kt * 16 + ac0, 16);
            cpa16(da1, x + (size_t)(n0 + ar1) * 256 + kt * 16 + ac1, 16);
            cpa16(db,  lw + (size_t)(kt * 16 + br) * 256 + bn * 64 + bc, 16);
        } else {
            // tail: k = 256..263 from ohfeat / lw rows 256..263; rest zero-fill
            cpa16(da0, (ac0 < 8) ? (const void*)(g_ohfeat + (n0 + ar0) * 8 + ac0)
                                 : (const void*)g_ohfeat, (ac0 < 8) ? 16 : 0);
            cpa16(da1, (ac1 < 8) ? (const void*)(g_ohfeat + (n0 + ar1) * 8 + ac1)
                                 : (const void*)g_ohfeat, (ac1 < 8) ? 16 : 0);
            cpa16(db,  (br < 8) ? (const void*)(lw + (size_t)(256 + br) * 256 + bn * 64 + bc)
                                : (const void*)lw, (br < 8) ? 16 : 0);
        }
        asm volatile("cp.async.commit_group;");
    };

    float c[2][4][4];
#pragma unroll
    for (int mt = 0; mt < 2; mt++)
#pragma unroll
        for (int nt = 0; nt < 4; nt++)
#pragma unroll
            for (int q = 0; q < 4; q++) c[mt][nt][q] = 0.f;

    stage(0);

    for (int kt = 0; kt < 17; kt++) {
        asm volatile("cp.async.wait_group 0;");
        __syncthreads();
        if (kt < 16) stage(kt + 1);

        const float* A = sA[kt & 1];
        const float* B = sB[kt & 1];
#pragma unroll
        for (int ks = 0; ks < 2; ks++) {
            int kbv = ks * 8;
            unsigned a[2][4], b[4][2];
#pragma unroll
            for (int mt = 0; mt < 2; mt++) {
                int m = wm * 32 + mt * 16 + gid;
                a[mt][0] = f2tf32(A[m       * ASTRIDE + kbv + tig]);
                a[mt][1] = f2tf32(A[(m + 8) * ASTRIDE + kbv + tig]);
                a[mt][2] = f2tf32(A[m       * ASTRIDE + kbv + tig + 4]);
                a[mt][3] = f2tf32(A[(m + 8) * ASTRIDE + kbv + tig + 4]);
            }
#pragma unroll
            for (int nt = 0; nt < 4; nt++) {
                int n = wn * 32 + nt * 8 + gid;
                b[nt][0] = f2tf32(B[(kbv + tig)     * BSTRIDE + n]);
                b[nt][1] = f2tf32(B[(kbv + tig + 4) * BSTRIDE + n]);
            }
#pragma unroll
            for (int mt = 0; mt < 2; mt++)
#pragma unroll
                for (int nt = 0; nt < 4; nt++)
                    asm volatile(
                        "mma.sync.aligned.m16n8k8.row.col.f32.tf32.tf32.f32 "
                        "{%0,%1,%2,%3}, {%4,%5,%6,%7}, {%8,%9}, {%0,%1,%2,%3};"
                        : "+f"(c[mt][nt][0]), "+f"(c[mt][nt][1]),
                          "+f"(c[mt][nt][2]), "+f"(c[mt][nt][3])
                        : "r"(a[mt][0]), "r"(a[mt][1]), "r"(a[mt][2]), "r"(a[mt][3]),
                          "r"(b[nt][0]), "r"(b[nt][1]));
        }
        __syncthreads();
    }

    // ---- store xp ----
#pragma unroll
    for (int mt = 0; mt < 2; mt++) {
        int r0 = wm * 32 + mt * 16 + gid;
#pragma unroll
        for (int nt = 0; nt < 4; nt++) {
            int gcol = bn * 64 + wn * 32 + nt * 8 + tig * 2;
            *(float2*)&g_xp[(size_t)(n0 + r0)     * 256 + gcol] =
                make_float2(c[mt][nt][0], c[mt][nt][1]);
            *(float2*)&g_xp[(size_t)(n0 + r0 + 8) * 256 + gcol] =
                make_float2(c[mt][nt][2], c[mt][nt][3]);
        }
    }

    // ---- fused alpha (this block's head = bn) ----
    float pl[4] = {0.f, 0.f, 0.f, 0.f};
    float pr[4] = {0.f, 0.f, 0.f, 0.f};
#pragma unroll
    for (int mt = 0; mt < 2; mt++)
#pragma unroll
        for (int nt = 0; nt < 4; nt++) {
            int cl = wn * 32 + nt * 8 + tig * 2;
            float wl0 = sattl[cl], wl1 = sattl[cl + 1];
            float wr0 = sattr[cl], wr1 = sattr[cl + 1];
            pl[mt*2+0] += c[mt][nt][0]*wl0 + c[mt][nt][1]*wl1;
            pl[mt*2+1] += c[mt][nt][2]*wl0 + c[mt][nt][3]*wl1;
            pr[mt*2+0] += c[mt][nt][0]*wr0 + c[mt][nt][1]*wr1;
            pr[mt*2+1] += c[mt][nt][2]*wr0 + c[mt][nt][3]*wr1;
        }
#pragma unroll
    for (int o = 2; o > 0; o >>= 1)
#pragma unroll
        for (int q = 0; q < 4; q++) {
            pl[q] += __shfl_down_sync(0xffffffffu, pl[q], o, 4);
            pr[q] += __shfl_down_sync(0xffffffffu, pr[q], o, 4);
        }
    if (tig == 0) {
#pragma unroll
        for (int mt = 0; mt < 2; mt++)
#pragma unroll
            for (int sb = 0; sb < 2; sb++) {
                int r = wm * 32 + mt * 16 + sb * 8 + gid;
                sredl[wn][r] = pl[mt*2+sb];
                sredr[wn][r] = pr[mt*2+sb];
            }
    }
    __syncthreads();
    if (t < 128) {
        g_al[(n0 + t) * 4 + bn] = sredl[0][t] + sredl[1][t];
        g_ar[(n0 + t) * 4 + bn] = sredr[0][t] + sredr[1][t];
    }
}

// ---------------------------------------------------------------------------
// 5. Combined gather-side aggregation: attention softmax-weighted sum of xp,
//    and onehot row scatter-add (gather form) + residual.
#define CHUNK 128
__global__ void __launch_bounds__(256) k_agg(
    const float* __restrict__ oh,
    const float* __restrict__ bias,
    float* __restrict__ out)
{
    __shared__ int   ssrc[CHUNK];
    __shared__ float sal[CHUNK * 4];

    int n = blockIdx.x, t = threadIdx.x;
    int g = n >> 8;
    int h = t >> 6;
    float arh = g_ar[n * 4 + h];
    const float* ohg = oh + (size_t)g * (NPG * NPG);

    float accx = 0.f, den = 0.f;
    float acco = ohg[(size_t)(n & 255) * 256 + t];   // residual term

    int beg = g_off[n];
    int cnt = g_deg[n];

    for (int c0 = 0; c0 < cnt; c0 += CHUNK) {
        int m = min(CHUNK, cnt - c0);
        __syncthreads();
        if (t < m) {
            int s = g_esrc[beg + c0 + t];
            ssrc[t] = s;
            float4 v = *(const float4*)&g_al[s * 4];
            sal[t*4 + 0] = v.x; sal[t*4 + 1] = v.y;
            sal[t*4 + 2] = v.z; sal[t*4 + 3] = v.w;
        }
        __syncthreads();
#pragma unroll 4
        for (int i = 0; i < m; i++) {
            int s = ssrc[i];
            float l = sal[i*4 + h] + arh;
            l = (l > 0.f) ? l : 0.2f * l;              // leaky_relu
            float w = __expf(l);
            den  += w;
            accx  = fmaf(w, g_xp[(size_t)s * 256 + t], accx);
            acco += ohg[(size_t)(s & 255) * 256 + t];
        }
    }

    out[(size_t)n * 256 + t] = accx / (den + 1e-16f) + bias[t];
    out[(size_t)NN * 256 + (size_t)n * 256 + t] = acco;
}

// ---------------------------------------------------------------------------
extern "C" void kernel_launch(void* const* d_in, const int* in_sizes, int n_in,
                              void* d_out, int out_size)
{
    const float* x     = (const float*)d_in[0];
    const float* oh    = (const float*)d_in[1];
    const int*   adjs  = (const int*)d_in[2];
    const float* lin_w = (const float*)d_in[3];
    const float* att_l = (const float*)d_in[4];
    const float* att_r = (const float*)d_in[5];
    const float* bias  = (const float*)d_in[6];
    const float* c1w   = (const float*)d_in[7];
    const float* c1b   = (const float*)d_in[8];
    const float* c2w   = (const float*)d_in[9];
    const float* c2b   = (const float*)d_in[10];
    const float* fcw   = (const float*)d_in[11];
    const float* fcb   = (const float*)d_in[12];
    float* out = (float*)d_out;

    // CSR build
    k_csr<<<G_, 256>>>(adjs);
    k_scatter<<<EE / 256, 256>>>(adjs);

    // node features
    k_conv<<<NN, 256>>>(oh, c1w, c1b, c2w, c2b, fcw, fcb);
    dim3 ggrid(NN / 128, 4);
    k_gemm<<<ggrid, 256>>>(x, lin_w, att_l, att_r);

    // aggregation + outputs
    k_agg<<<NN, 256>>>(oh, bias, out);
}

// round 8
// speedup vs baseline: 1.5462x; 1.0765x over previous
#include <cuda_runtime.h>
#include <math.h>

// Problem constants
#define G_    64
#define NPG   256
#define EPG   4096
#define NN    (G_*NPG)     // 16384 nodes
#define EE    (G_*EPG)     // 262144 edges
#define IN_C  256
#define OHC_  8
#define HH    4
#define CC    64
#define HC    256          // H*C
#define KDIM  (IN_C+OHC_)  // 264

typedef unsigned long long ull;

// Scratch (device globals; no allocation allowed)
__device__ int   g_deg[NN];
__device__ int   g_off[NN];
__device__ int   g_cur[NN];
__device__ int   g_esrc[EE];
__device__ __align__(16) float g_ohfeat[NN*OHC_];
__device__ __align__(16) float g_xp[NN*HC];
__device__ __align__(16) float g_al[NN*HH];
__device__ __align__(16) float g_ar[NN*HH];

// packed f32x2 helpers
__device__ __forceinline__ ull pack2(float lo, float hi) {
    ull r; asm("mov.b64 %0, {%1, %2};" : "=l"(r) : "f"(lo), "f"(hi)); return r;
}
__device__ __forceinline__ void unpack2(ull v, float& lo, float& hi) {
    asm("mov.b64 {%0, %1}, %2;" : "=f"(lo), "=f"(hi) : "l"(v));
}
#define FMA2(d, a, b, c) \
    asm("fma.rn.f32x2 %0, %1, %2, %3;" : "=l"(d) : "l"(a), "l"(b), "l"(c))

// ---------------------------------------------------------------------------
// 1. Fused CSR prefix: per-graph smem histogram + scan (one block per graph)
__global__ void __launch_bounds__(256) k_csr(const int* __restrict__ adjs) {
    __shared__ int sdeg[NPG];
    __shared__ int s[NPG];
    int g = blockIdx.x, t = threadIdx.x;
    sdeg[t] = 0;
    __syncthreads();
    const int* dsts = adjs + g * 2 * EPG + EPG;
#pragma unroll 4
    for (int e = t; e < EPG; e += 256)
        atomicAdd(&sdeg[dsts[e]], 1);
    __syncthreads();
    int d = sdeg[t];
    s[t] = d;
    for (int o = 1; o < NPG; o <<= 1) {
        __syncthreads();
        int v = (t >= o) ? s[t - o] : 0;
        __syncthreads();
        s[t] += v;
    }
    __syncthreads();
    int off = g * EPG + s[t] - d;   // exclusive prefix + graph base
    g_deg[g * NPG + t] = d;
    g_off[g * NPG + t] = off;
    g_cur[g * NPG + t] = off;
}

// 2. Scatter source ids into CSR slots
__global__ void k_scatter(const int* __restrict__ adjs) {
    int e  = blockIdx.x * 256 + threadIdx.x;
    if (e >= EE) return;
    int g  = e >> 12;
    int le = e & (EPG - 1);
    int base = g * 2 * EPG;
    int src = adjs[base + le];
    int dst = adjs[base + EPG + le];
    int pos = atomicAdd(&g_cur[g * NPG + dst], 1);
    g_esrc[pos] = g * NPG + src;
}

// ---------------------------------------------------------------------------
// 3. Per-node: sort row (register bitonic + shfl), conv1(1->8),
//    conv2(8->16) with packed f32x2 FMA, mean, fc -> oh_feat
__global__ void __launch_bounds__(256) k_conv(
    const float* __restrict__ oh,
    const float* __restrict__ w1, const float* __restrict__ b1,
    const float* __restrict__ w2, const float* __restrict__ b2,
    const float* __restrict__ fcw, const float* __restrict__ fcb)
{
    __shared__ float s[256];
    __shared__ float z1[8][258];
    __shared__ ull   sw2p[24 * 8];   // [j][ocp] packed weight pairs
    __shared__ float sp[8 * 16];
    __shared__ float smean[16];

    int n = blockIdx.x, t = threadIdx.x;

    if (t < 192) {
        int j = t >> 3, p = t & 7;
        sw2p[j * 8 + p] = pack2(w2[(2 * p) * 24 + j], w2[(2 * p + 1) * 24 + j]);
    }

    // --- bitonic sort, value in register; shfl for j<32, smem for j>=32 ---
    float v = oh[(size_t)n * 256 + t];
#pragma unroll
    for (int k = 2; k <= 256; k <<= 1) {
        for (int j = k >> 1; j > 0; j >>= 1) {
            float o;
            if (j >= 32) {
                __syncthreads();
                s[t] = v;
                __syncthreads();
                o = s[t ^ j];
            } else {
                o = __shfl_xor_sync(0xffffffffu, v, j);
            }
            bool up    = ((t & k) == 0);
            bool lower = ((t & j) == 0);
            v = (lower == up) ? fminf(v, o) : fmaxf(v, o);
        }
    }
    __syncthreads();
    s[t] = v;
    __syncthreads();

    // --- conv1: 1 -> 8 channels, k=3, zero 'same' padding, relu ---
    float left  = (t > 0)   ? s[t - 1] : 0.f;
    float mid   = s[t];
    float right = (t < 255) ? s[t + 1] : 0.f;
#pragma unroll
    for (int oc = 0; oc < 8; oc++) {
        float z = b1[oc] + w1[oc*3 + 0]*left + w1[oc*3 + 1]*mid + w1[oc*3 + 2]*right;
        z1[oc][t + 1] = fmaxf(z, 0.f);
    }
    if (t < 8)       z1[t][0]       = 0.f;
    else if (t < 16) z1[t - 8][257] = 0.f;
    __syncthreads();

    // --- conv2: 8 -> 16 channels via packed f32x2 (channel pairs), relu ---
    float tap[24];
#pragma unroll
    for (int ic = 0; ic < 8; ic++) {
        tap[ic*3 + 0] = z1[ic][t];
        tap[ic*3 + 1] = z1[ic][t + 1];
        tap[ic*3 + 2] = z1[ic][t + 2];
    }
    ull acc2[8];
#pragma unroll
    for (int p = 0; p < 8; p++) acc2[p] = pack2(b2[2*p], b2[2*p + 1]);
#pragma unroll
    for (int j = 0; j < 24; j++) {
        ull tp = pack2(tap[j], tap[j]);
#pragma unroll
        for (int p = 0; p < 8; p++)
            FMA2(acc2[p], sw2p[j * 8 + p], tp, acc2[p]);
    }
    float acc[16];
#pragma unroll
    for (int p = 0; p < 8; p++) {
        float a0, a1;
        unpack2(acc2[p], a0, a1);
        acc[2*p]     = fmaxf(a0, 0.f);
        acc[2*p + 1] = fmaxf(a1, 0.f);
    }

    // --- multi-channel butterfly reduce over the 32 lanes ---
    int lane = t & 31, wid = t >> 5;
    {
        bool lo = (lane & 16) == 0;
#pragma unroll
        for (int c2 = 0; c2 < 8; c2++) {
            float give = lo ? acc[c2 + 8] : acc[c2];
            float keep = lo ? acc[c2]     : acc[c2 + 8];
            acc[c2] = keep + __shfl_xor_sync(0xffffffffu, give, 16);
        }
    }
    {
        bool lo = (lane & 8) == 0;
#pragma unroll
        for (int c2 = 0; c2 < 4; c2++) {
            float give = lo ? acc[c2 + 4] : acc[c2];
            float keep = lo ? acc[c2]     : acc[c2 + 4];
            acc[c2] = keep + __shfl_xor_sync(0xffffffffu, give, 8);
        }
    }
    {
        bool lo = (lane & 4) == 0;
#pragma unroll
        for (int c2 = 0; c2 < 2; c2++) {
            float give = lo ? acc[c2 + 2] : acc[c2];
            float keep = lo ? acc[c2]     : acc[c2 + 2];
            acc[c2] = keep + __shfl_xor_sync(0xffffffffu, give, 4);
        }
    }
    {
        bool lo = (lane & 2) == 0;
        float give = lo ? acc[1] : acc[0];
        float keep = lo ? acc[0] : acc[1];
        acc[0] = keep + __shfl_xor_sync(0xffffffffu, give, 2);
    }
    acc[0] += __shfl_xor_sync(0xffffffffu, acc[0], 1);
    if ((lane & 1) == 0) sp[wid * 16 + (lane >> 1)] = acc[0];
    __syncthreads();
    if (t < 16) {
        float m = 0.f;
#pragma unroll
        for (int w = 0; w < 8; w++) m += sp[w * 16 + t];
        smean[t] = m * (1.0f / 256.0f);
    }
    __syncthreads();
    if (t < 8) {
        float z = fcb[t];
#pragma unroll
        for (int ic = 0; ic < 16; ic++) z = fmaf(smean[ic], fcw[ic * 8 + t], z);
        g_ohfeat[n * 8 + t] = z;
    }
}

// ---------------------------------------------------------------------------
// 4. Tensor-core GEMM with cp.async double buffering (unchanged from R7).
__device__ __forceinline__ unsigned f2tf32(float f) {
    unsigned u;
    asm("cvt.rna.tf32.f32 %0, %1;" : "=r"(u) : "f"(f));
    return u;
}
__device__ __forceinline__ void cpa16(unsigned d, const void* s, int srcsize) {
    asm volatile("cp.async.cg.shared.global [%0], [%1], 16, %2;"
                 :: "r"(d), "l"(s), "r"(srcsize));
}

#define ASTRIDE 20
#define BSTRIDE 72

__global__ void __launch_bounds__(256) k_gemm(
    const float* __restrict__ x, const float* __restrict__ lw,
    const float* __restrict__ attl, const float* __restrict__ attr)
{
    __shared__ float sA[2][128 * ASTRIDE];
    __shared__ float sB[2][16 * BSTRIDE];
    __shared__ float sattl[64], sattr[64];
    __shared__ float sredl[2][128], sredr[2][128];

    int t  = threadIdx.x;
    int bm = blockIdx.x, bn = blockIdx.y;      // bn == head
    int n0 = bm * 128;
    int w = t >> 5, lane = t & 31;
    int wm = w & 3, wn = w >> 2;
    int gid = lane >> 2, tig = lane & 3;

    if (t < 64) { sattl[t] = attl[bn * 64 + t]; sattr[t] = attr[bn * 64 + t]; }

    unsigned sAaddr[2], sBaddr[2];
    sAaddr[0] = (unsigned)__cvta_generic_to_shared(&sA[0][0]);
    sAaddr[1] = (unsigned)__cvta_generic_to_shared(&sA[1][0]);
    sBaddr[0] = (unsigned)__cvta_generic_to_shared(&sB[0][0]);
    sBaddr[1] = (unsigned)__cvta_generic_to_shared(&sB[1][0]);

    int ar0 = t >> 2,            ac0 = (t & 3) * 4;
    int ar1 = (t + 256) >> 2,    ac1 = (t & 3) * 4;
    int br  = t >> 4,            bc  = (t & 15) * 4;

    auto stage = [&](int kt) {
        int b = kt & 1;
        unsigned da0 = sAaddr[b] + (ar0 * ASTRIDE + ac0) * 4;
        unsigned da1 = sAaddr[b] + (ar1 * ASTRIDE + ac1) * 4;
        unsigned db  = sBaddr[b] + (br  * BSTRIDE + bc ) * 4;
        if (kt < 16) {
            cpa16(da0, x + (size_t)(n0 + ar0) * 256 + kt * 16 + ac0, 16);
            cpa16(da1, x + (size_t)(n0 + ar1) * 256 + kt * 16 + ac1, 16);
            cpa16(db,  lw + (size_t)(kt * 16 + br) * 256 + bn * 64 + bc, 16);
        } else {
            cpa16(da0, (ac0 < 8) ? (const void*)(g_ohfeat + (n0 + ar0) * 8 + ac0)
                                 : (const void*)g_ohfeat, (ac0 < 8) ? 16 : 0);
            cpa16(da1, (ac1 < 8) ? (const void*)(g_ohfeat + (n0 + ar1) * 8 + ac1)
                                 : (const void*)g_ohfeat, (ac1 < 8) ? 16 : 0);
            cpa16(db,  (br < 8) ? (const void*)(lw + (size_t)(256 + br) * 256 + bn * 64 + bc)
                                : (const void*)lw, (br < 8) ? 16 : 0);
        }
        asm volatile("cp.async.commit_group;");
    };

    float c[2][4][4];
#pragma unroll
    for (int mt = 0; mt < 2; mt++)
#pragma unroll
        for (int nt = 0; nt < 4; nt++)
#pragma unroll
            for (int q = 0; q < 4; q++) c[mt][nt][q] = 0.f;

    stage(0);

    for (int kt = 0; kt < 17; kt++) {
        asm volatile("cp.async.wait_group 0;");
        __syncthreads();
        if (kt < 16) stage(kt + 1);

        const float* A = sA[kt & 1];
        const float* B = sB[kt & 1];
#pragma unroll
        for (int ks = 0; ks < 2; ks++) {
            int kbv = ks * 8;
            unsigned a[2][4], b[4][2];
#pragma unroll
            for (int mt = 0; mt < 2; mt++) {
                int m = wm * 32 + mt * 16 + gid;
                a[mt][0] = f2tf32(A[m       * ASTRIDE + kbv + tig]);
                a[mt][1] = f2tf32(A[(m + 8) * ASTRIDE + kbv + tig]);
                a[mt][2] = f2tf32(A[m       * ASTRIDE + kbv + tig + 4]);
                a[mt][3] = f2tf32(A[(m + 8) * ASTRIDE + kbv + tig + 4]);
            }
#pragma unroll
            for (int nt = 0; nt < 4; nt++) {
                int n = wn * 32 + nt * 8 + gid;
                b[nt][0] = f2tf32(B[(kbv + tig)     * BSTRIDE + n]);
                b[nt][1] = f2tf32(B[(kbv + tig + 4) * BSTRIDE + n]);
            }
#pragma unroll
            for (int mt = 0; mt < 2; mt++)
#pragma unroll
                for (int nt = 0; nt < 4; nt++)
                    asm volatile(
                        "mma.sync.aligned.m16n8k8.row.col.f32.tf32.tf32.f32 "
                        "{%0,%1,%2,%3}, {%4,%5,%6,%7}, {%8,%9}, {%0,%1,%2,%3};"
                        : "+f"(c[mt][nt][0]), "+f"(c[mt][nt][1]),
                          "+f"(c[mt][nt][2]), "+f"(c[mt][nt][3])
                        : "r"(a[mt][0]), "r"(a[mt][1]), "r"(a[mt][2]), "r"(a[mt][3]),
                          "r"(b[nt][0]), "r"(b[nt][1]));
        }
        __syncthreads();
    }

    // ---- store xp ----
#pragma unroll
    for (int mt = 0; mt < 2; mt++) {
        int r0 = wm * 32 + mt * 16 + gid;
#pragma unroll
        for (int nt = 0; nt < 4; nt++) {
            int gcol = bn * 64 + wn * 32 + nt * 8 + tig * 2;
            *(float2*)&g_xp[(size_t)(n0 + r0)     * 256 + gcol] =
                make_float2(c[mt][nt][0], c[mt][nt][1]);
            *(float2*)&g_xp[(size_t)(n0 + r0 + 8) * 256 + gcol] =
                make_float2(c[mt][nt][2], c[mt][nt][3]);
        }
    }

    // ---- fused alpha (this block's head = bn) ----
    float pl[4] = {0.f, 0.f, 0.f, 0.f};
    float pr[4] = {0.f, 0.f, 0.f, 0.f};
#pragma unroll
    for (int mt = 0; mt < 2; mt++)
#pragma unroll
        for (int nt = 0; nt < 4; nt++) {
            int cl = wn * 32 + nt * 8 + tig * 2;
            float wl0 = sattl[cl], wl1 = sattl[cl + 1];
            float wr0 = sattr[cl], wr1 = sattr[cl + 1];
            pl[mt*2+0] += c[mt][nt][0]*wl0 + c[mt][nt][1]*wl1;
            pl[mt*2+1] += c[mt][nt][2]*wl0 + c[mt][nt][3]*wl1;
            pr[mt*2+0] += c[mt][nt][0]*wr0 + c[mt][nt][1]*wr1;
            pr[mt*2+1] += c[mt][nt][2]*wr0 + c[mt][nt][3]*wr1;
        }
#pragma unroll
    for (int o = 2; o > 0; o >>= 1)
#pragma unroll
        for (int q = 0; q < 4; q++) {
            pl[q] += __shfl_down_sync(0xffffffffu, pl[q], o, 4);
            pr[q] += __shfl_down_sync(0xffffffffu, pr[q], o, 4);
        }
    if (tig == 0) {
#pragma unroll
        for (int mt = 0; mt < 2; mt++)
#pragma unroll
            for (int sb = 0; sb < 2; sb++) {
                int r = wm * 32 + mt * 16 + sb * 8 + gid;
                sredl[wn][r] = pl[mt*2+sb];
                sredr[wn][r] = pr[mt*2+sb];
            }
    }
    __syncthreads();
    if (t < 128) {
        g_al[(n0 + t) * 4 + bn] = sredl[0][t] + sredl[1][t];
        g_ar[(n0 + t) * 4 + bn] = sredr[0][t] + sredr[1][t];
    }
}

// ---------------------------------------------------------------------------
// 5. Gather-side aggregation, vectorized: 64 col-threads x 4 edge slots.
//    Each thread covers 4 columns (float4), slots process edges i, i+4, ...
#define CHUNK 128
__global__ void __launch_bounds__(256) k_agg(
    const float* __restrict__ oh,
    const float* __restrict__ bias,
    float* __restrict__ out)
{
    __shared__ int   ssrc[CHUNK];
    __shared__ float sal[CHUNK * 4];
    __shared__ float sfx[4][256];
    __shared__ float sfo[4][256];
    __shared__ float sden[4][4];

    int n = blockIdx.x, t = threadIdx.x;
    int g = n >> 8;
    int slot = t >> 6;          // 0..3
    int c    = t & 63;          // col group -> cols c*4 .. c*4+3
    int col0 = c * 4;
    int h    = c >> 4;          // head
    float arh = g_ar[n * 4 + h];
    const float* ohg = oh + (size_t)g * (NPG * NPG);

    float4 accx = make_float4(0.f, 0.f, 0.f, 0.f);
    float4 acco = make_float4(0.f, 0.f, 0.f, 0.f);
    float  den  = 0.f;

    int beg = g_off[n];
    int cnt = g_deg[n];

    for (int cb = 0; cb < cnt; cb += CHUNK) {
        int m = min(CHUNK, cnt - cb);
        __syncthreads();
        if (t < m) {
            int s = g_esrc[beg + cb + t];
            ssrc[t] = s;
            float4 v = *(const float4*)&g_al[s * 4];
            sal[t*4 + 0] = v.x; sal[t*4 + 1] = v.y;
            sal[t*4 + 2] = v.z; sal[t*4 + 3] = v.w;
        }
        __syncthreads();
#pragma unroll 2
        for (int i = slot; i < m; i += 4) {
            int s = ssrc[i];
            float l = sal[i*4 + h] + arh;
            l = (l > 0.f) ? l : 0.2f * l;              // leaky_relu
            float w = __expf(l);
            den += w;
            float4 xv = *(const float4*)&g_xp[(size_t)s * 256 + col0];
            accx.x = fmaf(w, xv.x, accx.x);
            accx.y = fmaf(w, xv.y, accx.y);
            accx.z = fmaf(w, xv.z, accx.z);
            accx.w = fmaf(w, xv.w, accx.w);
            float4 ov = *(const float4*)&ohg[(size_t)(s & 255) * 256 + col0];
            acco.x += ov.x; acco.y += ov.y; acco.z += ov.z; acco.w += ov.w;
        }
    }

    *(float4*)&sfx[slot][col0] = accx;
    *(float4*)&sfo[slot][col0] = acco;
    if ((c & 15) == 0) sden[slot][h] = den;
    __syncthreads();

    int col = t;
    int hh  = col >> 6;
    float dsum = sden[0][hh] + sden[1][hh] + sden[2][hh] + sden[3][hh] + 1e-16f;
    float xsum = sfx[0][col] + sfx[1][col] + sfx[2][col] + sfx[3][col];
    float osum = sfo[0][col] + sfo[1][col] + sfo[2][col] + sfo[3][col]
               + ohg[(size_t)(n & 255) * 256 + col];
    out[(size_t)n * 256 + col] = xsum / dsum + bias[col];
    out[(size_t)NN * 256 + (size_t)n * 256 + col] = osum;
}

// ---------------------------------------------------------------------------
extern "C" void kernel_launch(void* const* d_in, const int* in_sizes, int n_in,
                              void* d_out, int out_size)
{
    const float* x     = (const float*)d_in[0];
    const float* oh    = (const float*)d_in[1];
    const int*   adjs  = (const int*)d_in[2];
    const float* lin_w = (const float*)d_in[3];
    const float* att_l = (const float*)d_in[4];
    const float* att_r = (const float*)d_in[5];
    const float* bias  = (const float*)d_in[6];
    const float* c1w   = (const float*)d_in[7];
    const float* c1b   = (const float*)d_in[8];
    const float* c2w   = (const float*)d_in[9];
    const float* c2b   = (const float*)d_in[10];
    const float* fcw   = (const float*)d_in[11];
    const float* fcb   = (const float*)d_in[12];
    float* out = (float*)d_out;

    // CSR build
    k_csr<<<G_, 256>>>(adjs);
    k_scatter<<<EE / 256, 256>>>(adjs);

    // node features
    k_conv<<<NN, 256>>>(oh, c1w, c1b, c2w, c2b, fcw, fcb);
    dim3 ggrid(NN / 128, 4);
    k_gemm<<<ggrid, 256>>>(x, lin_w, att_l, att_r);

    // aggregation + outputs
    k_agg<<<NN, 256>>>(oh, bias, out);
}

// round 9
// speedup vs baseline: 1.8411x; 1.1907x over previous
#include <cuda_runtime.h>
#include <math.h>

// Problem constants
#define G_    64
#define NPG   256
#define EPG   4096
#define NN    (G_*NPG)     // 16384 nodes
#define EE    (G_*EPG)     // 262144 edges
#define IN_C  256
#define OHC_  8
#define HH    4
#define CC    64
#define HC    256          // H*C
#define KDIM  (IN_C+OHC_)  // 264

typedef unsigned long long ull;

// Scratch (device globals; no allocation allowed)
__device__ int   g_deg[NN];
__device__ int   g_off[NN];
__device__ int   g_cur[NN];
__device__ int   g_esrc[EE];
__device__ __align__(16) float g_ohfeat[NN*OHC_];
__device__ __align__(16) float g_xp[NN*HC];
__device__ __align__(16) float g_al[NN*HH];
__device__ __align__(16) float g_ar[NN*HH];

// packed f32x2 helpers
__device__ __forceinline__ ull pack2(float lo, float hi) {
    ull r; asm("mov.b64 %0, {%1, %2};" : "=l"(r) : "f"(lo), "f"(hi)); return r;
}
__device__ __forceinline__ void unpack2(ull v, float& lo, float& hi) {
    asm("mov.b64 {%0, %1}, %2;" : "=f"(lo), "=f"(hi) : "l"(v));
}
#define FMA2(d, a, b, c) \
    asm("fma.rn.f32x2 %0, %1, %2, %3;" : "=l"(d) : "l"(a), "l"(b), "l"(c))

// ---------------------------------------------------------------------------
// 1. Fused CSR prefix: per-graph smem histogram + scan (one block per graph)
__global__ void __launch_bounds__(256) k_csr(const int* __restrict__ adjs) {
    __shared__ int sdeg[NPG];
    __shared__ int s[NPG];
    int g = blockIdx.x, t = threadIdx.x;
    sdeg[t] = 0;
    __syncthreads();
    const int* dsts = adjs + g * 2 * EPG + EPG;
#pragma unroll 4
    for (int e = t; e < EPG; e += 256)
        atomicAdd(&sdeg[dsts[e]], 1);
    __syncthreads();
    int d = sdeg[t];
    s[t] = d;
    for (int o = 1; o < NPG; o <<= 1) {
        __syncthreads();
        int v = (t >= o) ? s[t - o] : 0;
        __syncthreads();
        s[t] += v;
    }
    __syncthreads();
    int off = g * EPG + s[t] - d;   // exclusive prefix + graph base
    g_deg[g * NPG + t] = d;
    g_off[g * NPG + t] = off;
    g_cur[g * NPG + t] = off;
}

// 2. Scatter source ids into CSR slots
__global__ void k_scatter(const int* __restrict__ adjs) {
    int e  = blockIdx.x * 256 + threadIdx.x;
    if (e >= EE) return;
    int g  = e >> 12;
    int le = e & (EPG - 1);
    int base = g * 2 * EPG;
    int src = adjs[base + le];
    int dst = adjs[base + EPG + le];
    int pos = atomicAdd(&g_cur[g * NPG + dst], 1);
    g_esrc[pos] = g * NPG + src;
}

// ---------------------------------------------------------------------------
// 3. Warp-per-node conv: register bitonic sort (8/lane), conv1 in regs with
//    shfl halos, z1 in per-lane smem rows, conv2 f32x2 position pairs with
//    2-pair weight reuse, warp-local reduce + fc. 128 threads = 4 nodes.
__global__ void __launch_bounds__(128) k_conv(
    const float* __restrict__ oh,
    const float* __restrict__ w1, const float* __restrict__ b1,
    const float* __restrict__ w2, const float* __restrict__ b2,
    const float* __restrict__ fcw, const float* __restrict__ fcb)
{
    // per-lane z1 rows: [warp][lane][ic*10 + slot], slot 0/9 = halos
    __shared__ __align__(16) float z1s[4][32][82];
    __shared__ ull   sw2b[16 * 24];
    __shared__ float sw1[24], sb1[8], sb2[16], sfcw[16 * 8], sfcb[8];
    __shared__ float smean[4][16];

    int t = threadIdx.x;
    int w = t >> 5, l = t & 31;
    int n = blockIdx.x * 4 + w;

    // ---- stage weights (one barrier in the whole kernel) ----
    for (int i = t; i < 384; i += 128) {
        int oc = i / 24, j = i % 24;
        float wv = w2[oc * 24 + j];
        sw2b[i] = pack2(wv, wv);
    }
    if (t < 24)  sw1[t] = w1[t];
    if (t < 8)   sb1[t] = b1[t];
    if (t < 16)  sb2[t] = b2[t];
    if (t < 128) sfcw[t] = fcw[t];
    if (t < 8)   sfcb[t] = fcb[t];
    __syncthreads();

    // ---- load 8 elements ----
    const float* ohrow = oh + (size_t)n * 256;
    float v[8];
    {
        float4 u0 = *(const float4*)&ohrow[l * 8];
        float4 u1 = *(const float4*)&ohrow[l * 8 + 4];
        v[0]=u0.x; v[1]=u0.y; v[2]=u0.z; v[3]=u0.w;
        v[4]=u1.x; v[5]=u1.y; v[6]=u1.z; v[7]=u1.w;
    }

    // ---- register bitonic sort of 256 (blocked: idx = l*8 + i) ----
    #define CS(i, j, up) { float _a=v[i], _b=v[j]; \
        v[i] = (up)?fminf(_a,_b):fmaxf(_a,_b); \
        v[j] = (up)?fmaxf(_a,_b):fminf(_a,_b); }
    #define LOCAL3(up) { \
        CS(0,4,up) CS(1,5,up) CS(2,6,up) CS(3,7,up) \
        CS(0,2,up) CS(1,3,up) CS(4,6,up) CS(5,7,up) \
        CS(0,1,up) CS(2,3,up) CS(4,5,up) CS(6,7,up) }
    #define CROSS(jl, up) { bool _lo = ((l & (jl)) == 0); \
        _Pragma("unroll") \
        for (int _i = 0; _i < 8; _i++) { \
            float _o = __shfl_xor_sync(0xffffffffu, v[_i], (jl)); \
            v[_i] = ((_lo == (up)) ? fminf(v[_i], _o) : fmaxf(v[_i], _o)); } }

    // k=2
    CS(0,1,true) CS(2,3,false) CS(4,5,true) CS(6,7,false)
    // k=4
    CS(0,2,true) CS(1,3,true) CS(4,6,false) CS(5,7,false)
    CS(0,1,true) CS(2,3,true) CS(4,5,false) CS(6,7,false)
    // k=8
    { bool up = ((l & 1) == 0);  LOCAL3(up) }
    // k=16
    { bool up = ((l & 2) == 0);  CROSS(1,up) LOCAL3(up) }
    // k=32
    { bool up = ((l & 4) == 0);  CROSS(2,up) CROSS(1,up) LOCAL3(up) }
    // k=64
    { bool up = ((l & 8) == 0);  CROSS(4,up) CROSS(2,up) CROSS(1,up) LOCAL3(up) }
    // k=128
    { bool up = ((l & 16) == 0); CROSS(8,up) CROSS(4,up) CROSS(2,up) CROSS(1,up) LOCAL3(up) }
    // k=256 (ascending)
    { const bool up = true;      CROSS(16,up) CROSS(8,up) CROSS(4,up) CROSS(2,up) CROSS(1,up) LOCAL3(up) }

    // ---- conv1: halos via shfl, write z1 rows (own lane only) ----
    float lh = __shfl_up_sync(0xffffffffu, v[7], 1);  if (l == 0)  lh = 0.f;
    float rh = __shfl_down_sync(0xffffffffu, v[0], 1); if (l == 31) rh = 0.f;

#pragma unroll
    for (int ic = 0; ic < 8; ic++) {
        float wm = sw1[ic*3 + 0], wc = sw1[ic*3 + 1], wp = sw1[ic*3 + 2];
        float bb = sb1[ic];
        float z[8];
        z[0] = fmaxf(bb + wm*lh   + wc*v[0] + wp*v[1], 0.f);
#pragma unroll
        for (int i = 1; i < 7; i++)
            z[i] = fmaxf(bb + wm*v[i-1] + wc*v[i] + wp*v[i+1], 0.f);
        z[7] = fmaxf(bb + wm*v[6] + wc*v[7] + wp*rh, 0.f);

        float h0 = __shfl_up_sync(0xffffffffu, z[7], 1);  if (l == 0)  h0 = 0.f;
        float h9 = __shfl_down_sync(0xffffffffu, z[0], 1); if (l == 31) h9 = 0.f;

        float* zr = &z1s[w][l][ic * 10];
        zr[0] = h0;
#pragma unroll
        for (int i = 0; i < 8; i++) zr[i + 1] = z[i];
        zr[9] = h9;
    }
    // z1s rows are private per lane: no sync needed.

    // ---- conv2 + mean: f32x2 position pairs, 2 pairs per weight load ----
    float mean[16];
#pragma unroll
    for (int oc = 0; oc < 16; oc++) mean[oc] = 0.f;

#pragma unroll
    for (int qq = 0; qq < 2; qq++) {
        ull tap[2][24];
#pragma unroll
        for (int q2 = 0; q2 < 2; q2++) {
            int q = qq * 2 + q2;
#pragma unroll
            for (int ic = 0; ic < 8; ic++) {
                const float* zr = &z1s[w][l][ic * 10];
                ull A = *(const ull*)&zr[2 * q];
                ull B = *(const ull*)&zr[2 * q + 2];
                float a0, a1, b0, b1;
                unpack2(A, a0, a1); unpack2(B, b0, b1);
                tap[q2][ic*3 + 0] = A;
                tap[q2][ic*3 + 1] = pack2(a1, b0);
                tap[q2][ic*3 + 2] = B;
            }
        }
#pragma unroll
        for (int oc = 0; oc < 16; oc++) {
            ull acc0 = pack2(sb2[oc], sb2[oc]);
            ull acc1 = acc0;
#pragma unroll
            for (int j = 0; j < 24; j++) {
                ull wv = sw2b[oc * 24 + j];
                FMA2(acc0, wv, tap[0][j], acc0);
                FMA2(acc1, wv, tap[1][j], acc1);
            }
            float r0, r1, r2, r3;
            unpack2(acc0, r0, r1); unpack2(acc1, r2, r3);
            mean[oc] += fmaxf(r0, 0.f) + fmaxf(r1, 0.f)
                      + fmaxf(r2, 0.f) + fmaxf(r3, 0.f);
        }
    }

    // ---- multi-channel butterfly reduce over 32 lanes ----
    {
        bool lo = (l & 16) == 0;
#pragma unroll
        for (int c2 = 0; c2 < 8; c2++) {
            float give = lo ? mean[c2 + 8] : mean[c2];
            float keep = lo ? mean[c2]     : mean[c2 + 8];
            mean[c2] = keep + __shfl_xor_sync(0xffffffffu, give, 16);
        }
    }
    {
        bool lo = (l & 8) == 0;
#pragma unroll
        for (int c2 = 0; c2 < 4; c2++) {
            float give = lo ? mean[c2 + 4] : mean[c2];
            float keep = lo ? mean[c2]     : mean[c2 + 4];
            mean[c2] = keep + __shfl_xor_sync(0xffffffffu, give, 8);
        }
    }
    {
        bool lo = (l & 4) == 0;
#pragma unroll
        for (int c2 = 0; c2 < 2; c2++) {
            float give = lo ? mean[c2 + 2] : mean[c2];
            float keep = lo ? mean[c2]     : mean[c2 + 2];
            mean[c2] = keep + __shfl_xor_sync(0xffffffffu, give, 4);
        }
    }
    {
        bool lo = (l & 2) == 0;
        float give = lo ? mean[1] : mean[0];
        float keep = lo ? mean[0] : mean[1];
        mean[0] = keep + __shfl_xor_sync(0xffffffffu, give, 2);
    }
    mean[0] += __shfl_xor_sync(0xffffffffu, mean[0], 1);
    if ((l & 1) == 0) smean[w][l >> 1] = mean[0] * (1.0f / 256.0f);
    __syncwarp();

    // ---- fc (8 outputs) ----
    if (l < 8) {
        float z = sfcb[l];
#pragma unroll
        for (int ic = 0; ic < 16; ic++) z = fmaf(smean[w][ic], sfcw[ic * 8 + l], z);
        g_ohfeat[n * 8 + l] = z;
    }
}

// ---------------------------------------------------------------------------
// 4. Tensor-core GEMM with cp.async double buffering (unchanged from R7).
__device__ __forceinline__ unsigned f2tf32(float f) {
    unsigned u;
    asm("cvt.rna.tf32.f32 %0, %1;" : "=r"(u) : "f"(f));
    return u;
}
__device__ __forceinline__ void cpa16(unsigned d, const void* s, int srcsize) {
    asm volatile("cp.async.cg.shared.global [%0], [%1], 16, %2;"
                 :: "r"(d), "l"(s), "r"(srcsize));
}

#define ASTRIDE 20
#define BSTRIDE 72

__global__ void __launch_bounds__(256) k_gemm(
    const float* __restrict__ x, const float* __restrict__ lw,
    const float* __restrict__ attl, const float* __restrict__ attr)
{
    __shared__ float sA[2][128 * ASTRIDE];
    __shared__ float sB[2][16 * BSTRIDE];
    __shared__ float sattl[64], sattr[64];
    __shared__ float sredl[2][128], sredr[2][128];

    int t  = threadIdx.x;
    int bm = blockIdx.x, bn = blockIdx.y;      // bn == head
    int n0 = bm * 128;
    int w = t >> 5, lane = t & 31;
    int wm = w & 3, wn = w >> 2;
    int gid = lane >> 2, tig = lane & 3;

    if (t < 64) { sattl[t] = attl[bn * 64 + t]; sattr[t] = attr[bn * 64 + t]; }

    unsigned sAaddr[2], sBaddr[2];
    sAaddr[0] = (unsigned)__cvta_generic_to_shared(&sA[0][0]);
    sAaddr[1] = (unsigned)__cvta_generic_to_shared(&sA[1][0]);
    sBaddr[0] = (unsigned)__cvta_generic_to_shared(&sB[0][0]);
    sBaddr[1] = (unsigned)__cvta_generic_to_shared(&sB[1][0]);

    int ar0 = t >> 2,            ac0 = (t & 3) * 4;
    int ar1 = (t + 256) >> 2,    ac1 = (t & 3) * 4;
    int br  = t >> 4,            bc  = (t & 15) * 4;

    auto stage = [&](int kt) {
        int b = kt & 1;
        unsigned da0 = sAaddr[b] + (ar0 * ASTRIDE + ac0) * 4;
        unsigned da1 = sAaddr[b] + (ar1 * ASTRIDE + ac1) * 4;
        unsigned db  = sBaddr[b] + (br  * BSTRIDE + bc ) * 4;
        if (kt < 16) {
            cpa16(da0, x + (size_t)(n0 + ar0) * 256 + kt * 16 + ac0, 16);
            cpa16(da1, x + (size_t)(n0 + ar1) * 256 + kt * 16 + ac1, 16);
            cpa16(db,  lw + (size_t)(kt * 16 + br) * 256 + bn * 64 + bc, 16);
        } else {
            cpa16(da0, (ac0 < 8) ? (const void*)(g_ohfeat + (n0 + ar0) * 8 + ac0)
                                 : (const void*)g_ohfeat, (ac0 < 8) ? 16 : 0);
            cpa16(da1, (ac1 < 8) ? (const void*)(g_ohfeat + (n0 + ar1) * 8 + ac1)
                                 : (const void*)g_ohfeat, (ac1 < 8) ? 16 : 0);
            cpa16(db,  (br < 8) ? (const void*)(lw + (size_t)(256 + br) * 256 + bn * 64 + bc)
                                : (const void*)lw, (br < 8) ? 16 : 0);
        }
        asm volatile("cp.async.commit_group;");
    };

    float c[2][4][4];
#pragma unroll
    for (int mt = 0; mt < 2; mt++)
#pragma unroll
        for (int nt = 0; nt < 4; nt++)
#pragma unroll
            for (int q = 0; q < 4; q++) c[mt][nt][q] = 0.f;

    stage(0);

    for (int kt = 0; kt < 17; kt++) {
        asm volatile("cp.async.wait_group 0;");
        __syncthreads();
        if (kt < 16) stage(kt + 1);

        const float* A = sA[kt & 1];
        const float* B = sB[kt & 1];
#pragma unroll
        for (int ks = 0; ks < 2; ks++) {
            int kbv = ks * 8;
            unsigned a[2][4], b[4][2];
#pragma unroll
            for (int mt = 0; mt < 2; mt++) {
                int m = wm * 32 + mt * 16 + gid;
                a[mt][0] = f2tf32(A[m       * ASTRIDE + kbv + tig]);
                a[mt][1] = f2tf32(A[(m + 8) * ASTRIDE + kbv + tig]);
                a[mt][2] = f2tf32(A[m       * ASTRIDE + kbv + tig + 4]);
                a[mt][3] = f2tf32(A[(m + 8) * ASTRIDE + kbv + tig + 4]);
            }
#pragma unroll
            for (int nt = 0; nt < 4; nt++) {
                int n = wn * 32 + nt * 8 + gid;
                b[nt][0] = f2tf32(B[(kbv + tig)     * BSTRIDE + n]);
                b[nt][1] = f2tf32(B[(kbv + tig + 4) * BSTRIDE + n]);
            }
#pragma unroll
            for (int mt = 0; mt < 2; mt++)
#pragma unroll
                for (int nt = 0; nt < 4; nt++)
                    asm volatile(
                        "mma.sync.aligned.m16n8k8.row.col.f32.tf32.tf32.f32 "
                        "{%0,%1,%2,%3}, {%4,%5,%6,%7}, {%8,%9}, {%0,%1,%2,%3};"
                        : "+f"(c[mt][nt][0]), "+f"(c[mt][nt][1]),
                          "+f"(c[mt][nt][2]), "+f"(c[mt][nt][3])
                        : "r"(a[mt][0]), "r"(a[mt][1]), "r"(a[mt][2]), "r"(a[mt][3]),
                          "r"(b[nt][0]), "r"(b[nt][1]));
        }
        __syncthreads();
    }

    // ---- store xp ----
#pragma unroll
    for (int mt = 0; mt < 2; mt++) {
        int r0 = wm * 32 + mt * 16 + gid;
#pragma unroll
        for (int nt = 0; nt < 4; nt++) {
            int gcol = bn * 64 + wn * 32 + nt * 8 + tig * 2;
            *(float2*)&g_xp[(size_t)(n0 + r0)     * 256 + gcol] =
                make_float2(c[mt][nt][0], c[mt][nt][1]);
            *(float2*)&g_xp[(size_t)(n0 + r0 + 8) * 256 + gcol] =
                make_float2(c[mt][nt][2], c[mt][nt][3]);
        }
    }

    // ---- fused alpha (this block's head = bn) ----
    float pl[4] = {0.f, 0.f, 0.f, 0.f};
    float pr[4] = {0.f, 0.f, 0.f, 0.f};
#pragma unroll
    for (int mt = 0; mt < 2; mt++)
#pragma unroll
        for (int nt = 0; nt < 4; nt++) {
            int cl = wn * 32 + nt * 8 + tig * 2;
            float wl0 = sattl[cl], wl1 = sattl[cl + 1];
            float wr0 = sattr[cl], wr1 = sattr[cl + 1];
            pl[mt*2+0] += c[mt][nt][0]*wl0 + c[mt][nt][1]*wl1;
            pl[mt*2+1] += c[mt][nt][2]*wl0 + c[mt][nt][3]*wl1;
            pr[mt*2+0] += c[mt][nt][0]*wr0 + c[mt][nt][1]*wr1;
            pr[mt*2+1] += c[mt][nt][2]*wr0 + c[mt][nt][3]*wr1;
        }
#pragma unroll
    for (int o = 2; o > 0; o >>= 1)
#pragma unroll
        for (int q = 0; q < 4; q++) {
            pl[q] += __shfl_down_sync(0xffffffffu, pl[q], o, 4);
            pr[q] += __shfl_down_sync(0xffffffffu, pr[q], o, 4);
        }
    if (tig == 0) {
#pragma unroll
        for (int mt = 0; mt < 2; mt++)
#pragma unroll
            for (int sb = 0; sb < 2; sb++) {
                int r = wm * 32 + mt * 16 + sb * 8 + gid;
                sredl[wn][r] = pl[mt*2+sb];
                sredr[wn][r] = pr[mt*2+sb];
            }
    }
    __syncthreads();
    if (t < 128) {
        g_al[(n0 + t) * 4 + bn] = sredl[0][t] + sredl[1][t];
        g_ar[(n0 + t) * 4 + bn] = sredr[0][t] + sredr[1][t];
    }
}

// ---------------------------------------------------------------------------
// 5. Gather-side aggregation, vectorized: 64 col-threads x 4 edge slots.
#define CHUNK 128
__global__ void __launch_bounds__(256) k_agg(
    const float* __restrict__ oh,
    const float* __restrict__ bias,
    float* __restrict__ out)
{
    __shared__ int   ssrc[CHUNK];
    __shared__ float sal[CHUNK * 4];
    __shared__ float sfx[4][256];
    __shared__ float sfo[4][256];
    __shared__ float sden[4][4];

    int n = blockIdx.x, t = threadIdx.x;
    int g = n >> 8;
    int slot = t >> 6;          // 0..3
    int c    = t & 63;          // col group -> cols c*4 .. c*4+3
    int col0 = c * 4;
    int h    = c >> 4;          // head
    float arh = g_ar[n * 4 + h];
    const float* ohg = oh + (size_t)g * (NPG * NPG);

    float4 accx = make_float4(0.f, 0.f, 0.f, 0.f);
    float4 acco = make_float4(0.f, 0.f, 0.f, 0.f);
    float  den  = 0.f;

    int beg = g_off[n];
    int cnt = g_deg[n];

    for (int cb = 0; cb < cnt; cb += CHUNK) {
        int m = min(CHUNK, cnt - cb);
        __syncthreads();
        if (t < m) {
            int s = g_esrc[beg + cb + t];
            ssrc[t] = s;
            float4 v = *(const float4*)&g_al[s * 4];
            sal[t*4 + 0] = v.x; sal[t*4 + 1] = v.y;
            sal[t*4 + 2] = v.z; sal[t*4 + 3] = v.w;
        }
        __syncthreads();
#pragma unroll 2
        for (int i = slot; i < m; i += 4) {
            int s = ssrc[i];
            float l = sal[i*4 + h] + arh;
            l = (l > 0.f) ? l : 0.2f * l;              // leaky_relu
            float w = __expf(l);
            den += w;
            float4 xv = *(const float4*)&g_xp[(size_t)s * 256 + col0];
            accx.x = fmaf(w, xv.x, accx.x);
            accx.y = fmaf(w, xv.y, accx.y);
            accx.z = fmaf(w, xv.z, accx.z);
            accx.w = fmaf(w, xv.w, accx.w);
            float4 ov = *(const float4*)&ohg[(size_t)(s & 255) * 256 + col0];
            acco.x += ov.x; acco.y += ov.y; acco.z += ov.z; acco.w += ov.w;
        }
    }

    *(float4*)&sfx[slot][col0] = accx;
    *(float4*)&sfo[slot][col0] = acco;
    if ((c & 15) == 0) sden[slot][h] = den;
    __syncthreads();

    int col = t;
    int hh  = col >> 6;
    float dsum = sden[0][hh] + sden[1][hh] + sden[2][hh] + sden[3][hh] + 1e-16f;
    float xsum = sfx[0][col] + sfx[1][col] + sfx[2][col] + sfx[3][col];
    float osum = sfo[0][col] + sfo[1][col] + sfo[2][col] + sfo[3][col]
               + ohg[(size_t)(n & 255) * 256 + col];
    out[(size_t)n * 256 + col] = xsum / dsum + bias[col];
    out[(size_t)NN * 256 + (size_t)n * 256 + col] = osum;
}

// ---------------------------------------------------------------------------
extern "C" void kernel_launch(void* const* d_in, const int* in_sizes, int n_in,
                              void* d_out, int out_size)
{
    const float* x     = (const float*)d_in[0];
    const float* oh    = (const float*)d_in[1];
    const int*   adjs  = (const int*)d_in[2];
    const float* lin_w = (const float*)d_in[3];
    const float* att_l = (const float*)d_in[4];
    const float* att_r = (const float*)d_in[5];
    const float* bias  = (const float*)d_in[6];
    const float* c1w   = (const float*)d_in[7];
    const float* c1b   = (const float*)d_in[8];
    const float* c2w   = (const float*)d_in[9];
    const float* c2b   = (const float*)d_in[10];
    const float* fcw   = (const float*)d_in[11];
    const float* fcb   = (const float*)d_in[12];
    float* out = (float*)d_out;

    // CSR build
    k_csr<<<G_, 256>>>(adjs);
    k_scatter<<<EE / 256, 256>>>(adjs);

    // node features
    k_conv<<<NN / 4, 128>>>(oh, c1w, c1b, c2w, c2b, fcw, fcb);
    dim3 ggrid(NN / 128, 4);
    k_gemm<<<ggrid, 256>>>(x, lin_w, att_l, att_r);

    // aggregation + outputs
    k_agg<<<NN, 256>>>(oh, bias, out);
}